// round 4
// baseline (speedup 1.0000x reference)
#include <cuda_runtime.h>
#include <cuda_bf16.h>
#include <math_constants.h>

// Problem constants
#define NSEQ 2048
#define DMODEL 1024
#define NHEAD 16
#define HDIM 64
#define QKV_W (3 * DMODEL)   // 3072

// ---------------------------------------------------------------------------
// Scratch (no allocations allowed; __device__ globals are the sanctioned path)
// ---------------------------------------------------------------------------
__device__ float g_qkv[NSEQ * QKV_W];     // [2048, 3072] q|k|v
__device__ float g_gate[NSEQ * DMODEL];   // sigmoid(x Wg^T + bg)
__device__ float g_attn[NSEQ * DMODEL];   // attn_out * gate

// ---------------------------------------------------------------------------
// SGEMM: C[M,Nn] = A[M,K] @ W[Nn,K]^T + bias[Nn]   (act=1 -> sigmoid epilogue)
// 128x128 block tile, BK=16, 256 threads, 8x8 per-thread tile.
// M % 128 == 0, Nn % 128 == 0, K % 16 == 0 (holds for all three calls).
// ---------------------------------------------------------------------------
#define BM 128
#define BN 128
#define BK 16
#define TM 8
#define TN 8

__global__ __launch_bounds__(256, 2)
void sgemm_bias(const float* __restrict__ A, const float* __restrict__ W,
                const float* __restrict__ bias, float* __restrict__ C,
                int M, int Nn, int K, int act)
{
    __shared__ __align__(16) float As[BK][BM + 4];
    __shared__ __align__(16) float Bs[BK][BN + 4];

    const int tid = threadIdx.x;
    const int tx = tid & 15;          // n sub-tile
    const int ty = tid >> 4;          // m sub-tile
    const int row0 = blockIdx.y * BM;
    const int col0 = blockIdx.x * BN;

    const int ld_row = tid >> 2;            // 0..63
    const int ld_col = (tid & 3) * 4;       // 0,4,8,12

    float acc[TM][TN];
#pragma unroll
    for (int i = 0; i < TM; i++)
#pragma unroll
        for (int j = 0; j < TN; j++) acc[i][j] = 0.0f;

    for (int k0 = 0; k0 < K; k0 += BK) {
#pragma unroll
        for (int r = 0; r < BM; r += 64) {
            float4 v = *(const float4*)&A[(size_t)(row0 + ld_row + r) * K + k0 + ld_col];
            As[ld_col + 0][ld_row + r] = v.x;
            As[ld_col + 1][ld_row + r] = v.y;
            As[ld_col + 2][ld_row + r] = v.z;
            As[ld_col + 3][ld_row + r] = v.w;
        }
#pragma unroll
        for (int r = 0; r < BN; r += 64) {
            float4 v = *(const float4*)&W[(size_t)(col0 + ld_row + r) * K + k0 + ld_col];
            Bs[ld_col + 0][ld_row + r] = v.x;
            Bs[ld_col + 1][ld_row + r] = v.y;
            Bs[ld_col + 2][ld_row + r] = v.z;
            Bs[ld_col + 3][ld_row + r] = v.w;
        }
        __syncthreads();

#pragma unroll
        for (int kk = 0; kk < BK; kk++) {
            float ra[TM], rb[TN];
            float4 a0 = *(const float4*)&As[kk][ty * TM + 0];
            float4 a1 = *(const float4*)&As[kk][ty * TM + 4];
            float4 b0 = *(const float4*)&Bs[kk][tx * TN + 0];
            float4 b1 = *(const float4*)&Bs[kk][tx * TN + 4];
            ra[0] = a0.x; ra[1] = a0.y; ra[2] = a0.z; ra[3] = a0.w;
            ra[4] = a1.x; ra[5] = a1.y; ra[6] = a1.z; ra[7] = a1.w;
            rb[0] = b0.x; rb[1] = b0.y; rb[2] = b0.z; rb[3] = b0.w;
            rb[4] = b1.x; rb[5] = b1.y; rb[6] = b1.z; rb[7] = b1.w;
#pragma unroll
            for (int i = 0; i < TM; i++)
#pragma unroll
                for (int j = 0; j < TN; j++)
                    acc[i][j] += ra[i] * rb[j];
        }
        __syncthreads();
    }

    // epilogue
    float bv[TN];
#pragma unroll
    for (int j = 0; j < TN; j++) bv[j] = bias[col0 + tx * TN + j];

#pragma unroll
    for (int i = 0; i < TM; i++) {
        const int r = row0 + ty * TM + i;
        float out[TN];
#pragma unroll
        for (int j = 0; j < TN; j++) {
            float c = acc[i][j] + bv[j];
            if (act) c = 1.0f / (1.0f + __expf(-c));
            out[j] = c;
        }
        float4* dst = (float4*)&C[(size_t)r * Nn + col0 + tx * TN];
        dst[0] = make_float4(out[0], out[1], out[2], out[3]);
        dst[1] = make_float4(out[4], out[5], out[6], out[7]);
    }
}

// ---------------------------------------------------------------------------
// Offset attention + gate fuse. One warp per (n, h) pair.
// Phase 1: lane-per-offset (3 offsets/lane) full-dim dot products (q in smem).
// Phase 2: warp-shuffle softmax over NO scores.
// Phase 3: dim-parallel (float2 per lane) weighted V sum, coalesced rows.
// ---------------------------------------------------------------------------
#define WPB 8   // warps per block

__global__ __launch_bounds__(WPB * 32)
void attn_kernel(const float* __restrict__ qkv, const float* __restrict__ gate,
                 const float* __restrict__ pos_bias, const int* __restrict__ offsets,
                 float* __restrict__ attn_out, int NO)
{
    __shared__ __align__(16) float q_sh[WPB][HDIM];
    __shared__ float sc_sh[WPB][96];
    __shared__ int offs_sh[96];

    const int tid = threadIdx.x;
    const int w = tid >> 5;
    const int l = tid & 31;

    for (int i = tid; i < NO; i += blockDim.x) offs_sh[i] = offsets[i];
    __syncthreads();

    const int pair = blockIdx.x * WPB + w;        // [0, NSEQ*NHEAD)
    const int n = pair >> 4;
    const int h = pair & 15;

    const float* qrow  = qkv + (size_t)n * QKV_W + h * HDIM;
    const float* Kbase = qkv + DMODEL     + h * HDIM;
    const float* Vbase = qkv + 2 * DMODEL + h * HDIM;

    // q -> shared
    float2 q2 = *(const float2*)(qrow + 2 * l);
    q_sh[w][2 * l]     = q2.x;
    q_sh[w][2 * l + 1] = q2.y;
    __syncwarp();

    // Phase 1: scores (lane handles offsets l, l+32, l+64)
    float sloc[3];
    float m = -CUDART_INF_F;
#pragma unroll
    for (int j = 0; j < 3; j++) {
        const int o = l + 32 * j;
        float s = -CUDART_INF_F;
        if (o < NO) {
            const int idx = n - offs_sh[o];
            if (idx >= 0) {
                const float* krow = Kbase + (size_t)idx * QKV_W;
                float a = 0.0f;
#pragma unroll
                for (int d = 0; d < HDIM; d += 4) {
                    float4 kv = *(const float4*)(krow + d);
                    float4 qv = *(const float4*)(&q_sh[w][d]);
                    a += kv.x * qv.x + kv.y * qv.y + kv.z * qv.z + kv.w * qv.w;
                }
                s = a * 0.125f + pos_bias[o * NHEAD + h];
            }
        }
        sloc[j] = s;
        m = fmaxf(m, s);
    }
#pragma unroll
    for (int off = 16; off > 0; off >>= 1)
        m = fmaxf(m, __shfl_xor_sync(0xFFFFFFFFu, m, off));

    float ssum = 0.0f;
    float eloc[3];
#pragma unroll
    for (int j = 0; j < 3; j++) {
        float e = (sloc[j] == -CUDART_INF_F) ? 0.0f : __expf(sloc[j] - m);
        eloc[j] = e;
        ssum += e;
    }
#pragma unroll
    for (int off = 16; off > 0; off >>= 1)
        ssum += __shfl_xor_sync(0xFFFFFFFFu, ssum, off);

    const float inv = 1.0f / ssum;
#pragma unroll
    for (int j = 0; j < 3; j++) {
        const int o = l + 32 * j;
        if (o < NO) sc_sh[w][o] = eloc[j] * inv;
    }
    __syncwarp();

    // Phase 3: output accumulation, lane covers dims (2l, 2l+1)
    float ax = 0.0f, ay = 0.0f;
    for (int o = 0; o < NO; o++) {
        const float a = sc_sh[w][o];
        int idx = n - offs_sh[o];
        if (idx < 0) idx = 0;                       // alpha==0 there anyway
        const float2 v2 = *(const float2*)(Vbase + (size_t)idx * QKV_W + 2 * l);
        ax += a * v2.x;
        ay += a * v2.y;
    }

    const int col = h * HDIM + 2 * l;
    const float2 g = *(const float2*)(gate + (size_t)n * DMODEL + col);
    float2 r;
    r.x = ax * g.x;
    r.y = ay * g.y;
    *(float2*)(attn_out + (size_t)n * DMODEL + col) = r;
}

// ---------------------------------------------------------------------------
// Launch
// ---------------------------------------------------------------------------
extern "C" void kernel_launch(void* const* d_in, const int* in_sizes, int n_in,
                              void* d_out, int out_size)
{
    const float* x        = (const float*)d_in[0];
    const float* Wqkv     = (const float*)d_in[1];
    const float* bqkv     = (const float*)d_in[2];
    const float* Wgate    = (const float*)d_in[3];
    const float* bgate    = (const float*)d_in[4];
    const float* Wout     = (const float*)d_in[5];
    const float* bout     = (const float*)d_in[6];
    const float* pos_bias = (const float*)d_in[7];
    const int*   offsets  = (const int*)d_in[8];
    const int NO = in_sizes[8];

    float *qkv_p, *gate_p, *attn_p;
    cudaGetSymbolAddress((void**)&qkv_p,  g_qkv);
    cudaGetSymbolAddress((void**)&gate_p, g_gate);
    cudaGetSymbolAddress((void**)&attn_p, g_attn);

    // 1) qkv = x @ Wqkv^T + bqkv
    sgemm_bias<<<dim3(QKV_W / BN, NSEQ / BM), 256>>>(
        x, Wqkv, bqkv, qkv_p, NSEQ, QKV_W, DMODEL, 0);

    // 2) gate = sigmoid(x @ Wgate^T + bgate)
    sgemm_bias<<<dim3(DMODEL / BN, NSEQ / BM), 256>>>(
        x, Wgate, bgate, gate_p, NSEQ, DMODEL, DMODEL, 1);

    // 3) attention + gate multiply
    attn_kernel<<<(NSEQ * NHEAD) / WPB, WPB * 32>>>(
        qkv_p, gate_p, pos_bias, offsets, attn_p, NO);

    // 4) out = (attn * gate) @ Wout^T + bout
    sgemm_bias<<<dim3(DMODEL / BN, NSEQ / BM), 256>>>(
        attn_p, Wout, bout, (float*)d_out, NSEQ, DMODEL, DMODEL, 0);
}

// round 7
// speedup vs baseline: 1.8578x; 1.8578x over previous
#include <cuda_runtime.h>
#include <cuda_bf16.h>
#include <math_constants.h>

// Problem constants
#define NSEQ 2048
#define DMODEL 1024
#define NHEAD 16
#define HDIM 64
#define QKV_W (3 * DMODEL)   // 3072

// ---------------------------------------------------------------------------
// Scratch (__device__ globals; no allocations allowed)
// ---------------------------------------------------------------------------
__device__ float g_qkv [NSEQ * QKV_W];     // q|k|v, fp32
__device__ float g_gate[NSEQ * DMODEL];    // sigmoid(x Wg^T + bg), fp32
__device__ float g_attn[NSEQ * DMODEL];    // (attn*gate), tf32-rounded
__device__ float g_xr   [NSEQ * DMODEL];   // tf32-rounded x
__device__ float g_wqkvr[QKV_W * DMODEL];  // tf32-rounded Wqkv
__device__ float g_wgatr[DMODEL * DMODEL]; // tf32-rounded Wgate
__device__ float g_woutr[DMODEL * DMODEL]; // tf32-rounded Wout

__device__ __forceinline__ float rna_tf32(float x) {
    float y;
    asm("cvt.rna.tf32.f32 %0, %1;" : "=f"(y) : "f"(x));
    return y;
}

// ---------------------------------------------------------------------------
// Elementwise tf32 rounding (float4 vectorized, grid-stride)
// ---------------------------------------------------------------------------
__global__ void round_kernel(const float4* __restrict__ in, float4* __restrict__ out, int n4)
{
    int i = blockIdx.x * blockDim.x + threadIdx.x;
    const int stride = gridDim.x * blockDim.x;
    for (; i < n4; i += stride) {
        float4 v = in[i];
        v.x = rna_tf32(v.x);
        v.y = rna_tf32(v.y);
        v.z = rna_tf32(v.z);
        v.w = rna_tf32(v.w);
        out[i] = v;
    }
}

// ---------------------------------------------------------------------------
// tf32 tensor-core GEMM: C[M,Nn] = A[M,K] @ W[Nn,K]^T + bias  (act=1: sigmoid)
// A and W must be tf32-pre-rounded fp32. 128x128 tile, BK=16, double-buffered
// cp.async pipeline, 8 warps, 32x64 warp tile, mma.sync.m16n8k8.
// ---------------------------------------------------------------------------
#define BM 128
#define BN 128
#define BKT 16
#define LDSD 20   // smem row stride in words (16 + 4 pad -> conflict-free frags)

__device__ __forceinline__ void mma16n8k8(float* c, const unsigned* a, const unsigned* b)
{
    asm volatile(
        "mma.sync.aligned.m16n8k8.row.col.f32.tf32.tf32.f32 "
        "{%0,%1,%2,%3}, {%4,%5,%6,%7}, {%8,%9}, {%0,%1,%2,%3};\n"
        : "+f"(c[0]), "+f"(c[1]), "+f"(c[2]), "+f"(c[3])
        : "r"(a[0]), "r"(a[1]), "r"(a[2]), "r"(a[3]), "r"(b[0]), "r"(b[1]));
}

#define CP16(sm, gp) \
    asm volatile("cp.async.cg.shared.global [%0], [%1], 16;\n" :: "r"(sm), "l"(gp) : "memory")

__global__ __launch_bounds__(256, 2)
void mma_gemm(const float* __restrict__ A, const float* __restrict__ W,
              const float* __restrict__ bias, float* __restrict__ C,
              int M, int Nn, int K, int act)
{
    __shared__ __align__(16) unsigned As[2][BM * LDSD];
    __shared__ __align__(16) unsigned Bs[2][BN * LDSD];

    const int tid  = threadIdx.x;
    const int lane = tid & 31;
    const int wid  = tid >> 5;
    const int wm   = wid & 3;          // 4 warps along M (32 rows each)
    const int wn   = wid >> 2;         // 2 warps along N (64 cols each)
    const int row0 = blockIdx.y * BM;
    const int col0 = blockIdx.x * BN;

    // copy mapping: thread covers (cpr, cpc..cpc+3) and (cpr+64, ...)
    const int cpr = tid >> 2;          // 0..63
    const int cpc = (tid & 3) * 4;     // 0,4,8,12

    const float* Ag = A + (size_t)(row0 + cpr) * K + cpc;
    const float* Wg = W + (size_t)(col0 + cpr) * K + cpc;

    unsigned sA[2], sB[2];
    sA[0] = (unsigned)__cvta_generic_to_shared(&As[0][cpr * LDSD + cpc]);
    sA[1] = (unsigned)__cvta_generic_to_shared(&As[1][cpr * LDSD + cpc]);
    sB[0] = (unsigned)__cvta_generic_to_shared(&Bs[0][cpr * LDSD + cpc]);
    sB[1] = (unsigned)__cvta_generic_to_shared(&Bs[1][cpr * LDSD + cpc]);
    const unsigned off64 = 64 * LDSD * 4;   // +64 rows, bytes
    const size_t   goff64 = (size_t)64 * K;

    float acc[2][8][4];
#pragma unroll
    for (int mt = 0; mt < 2; mt++)
#pragma unroll
        for (int nt = 0; nt < 8; nt++)
#pragma unroll
            for (int i = 0; i < 4; i++) acc[mt][nt][i] = 0.0f;

    const int T = K / BKT;

    // prologue: tile 0 -> buf 0
    CP16(sA[0],         Ag);
    CP16(sA[0] + off64, Ag + goff64);
    CP16(sB[0],         Wg);
    CP16(sB[0] + off64, Wg + goff64);
    asm volatile("cp.async.commit_group;\n" ::: "memory");

    const int qk = lane & 3;
    const int qr = lane >> 2;

    for (int t = 0; t < T; t++) {
        const int buf = t & 1;
        if (t + 1 < T) {
            const int nb = buf ^ 1;
            const int k1 = (t + 1) * BKT;
            CP16(sA[nb],         Ag + k1);
            CP16(sA[nb] + off64, Ag + k1 + goff64);
            CP16(sB[nb],         Wg + k1);
            CP16(sB[nb] + off64, Wg + k1 + goff64);
        }
        asm volatile("cp.async.commit_group;\n" ::: "memory");
        asm volatile("cp.async.wait_group 1;\n" ::: "memory");
        __syncthreads();

        const unsigned* as = As[buf];
        const unsigned* bs = Bs[buf];
#pragma unroll
        for (int ks = 0; ks < 2; ks++) {
            unsigned bfr[8][2];
#pragma unroll
            for (int nt = 0; nt < 8; nt++) {
                const int n = wn * 64 + nt * 8 + qr;
                bfr[nt][0] = bs[n * LDSD + ks * 8 + qk];
                bfr[nt][1] = bs[n * LDSD + ks * 8 + qk + 4];
            }
            unsigned afr[2][4];
#pragma unroll
            for (int mt = 0; mt < 2; mt++) {
                const int m = wm * 32 + mt * 16 + qr;
                afr[mt][0] = as[m * LDSD + ks * 8 + qk];
                afr[mt][1] = as[(m + 8) * LDSD + ks * 8 + qk];
                afr[mt][2] = as[m * LDSD + ks * 8 + qk + 4];
                afr[mt][3] = as[(m + 8) * LDSD + ks * 8 + qk + 4];
            }
#pragma unroll
            for (int mt = 0; mt < 2; mt++)
#pragma unroll
                for (int nt = 0; nt < 8; nt++)
                    mma16n8k8(acc[mt][nt], afr[mt], bfr[nt]);
        }
        __syncthreads();
    }

    // epilogue: bias (+ optional sigmoid), float2 stores
#pragma unroll
    for (int mt = 0; mt < 2; mt++) {
        const int r0 = row0 + wm * 32 + mt * 16 + qr;
#pragma unroll
        for (int nt = 0; nt < 8; nt++) {
            const int c = col0 + wn * 64 + nt * 8 + qk * 2;
            const float2 bv = *(const float2*)&bias[c];
            float v0 = acc[mt][nt][0] + bv.x;
            float v1 = acc[mt][nt][1] + bv.y;
            float v2 = acc[mt][nt][2] + bv.x;
            float v3 = acc[mt][nt][3] + bv.y;
            if (act) {
                v0 = 1.0f / (1.0f + __expf(-v0));
                v1 = 1.0f / (1.0f + __expf(-v1));
                v2 = 1.0f / (1.0f + __expf(-v2));
                v3 = 1.0f / (1.0f + __expf(-v3));
            }
            *(float2*)&C[(size_t)r0 * Nn + c]       = make_float2(v0, v1);
            *(float2*)&C[(size_t)(r0 + 8) * Nn + c] = make_float2(v2, v3);
        }
    }
}

// ---------------------------------------------------------------------------
// Offset attention + gate fuse. One warp per (n, h) pair.
// Output is tf32-rounded so it is a valid A operand for the out-projection.
// ---------------------------------------------------------------------------
#define WPB 8

__global__ __launch_bounds__(WPB * 32)
void attn_kernel(const float* __restrict__ qkv, const float* __restrict__ gate,
                 const float* __restrict__ pos_bias, const int* __restrict__ offsets,
                 float* __restrict__ attn_out, int NO)
{
    __shared__ __align__(16) float q_sh[WPB][HDIM];
    __shared__ float sc_sh[WPB][96];
    __shared__ int offs_sh[96];

    const int tid = threadIdx.x;
    const int w = tid >> 5;
    const int l = tid & 31;

    for (int i = tid; i < NO; i += blockDim.x) offs_sh[i] = offsets[i];
    __syncthreads();

    const int pair = blockIdx.x * WPB + w;
    const int n = pair >> 4;
    const int h = pair & 15;

    const float* qrow  = qkv + (size_t)n * QKV_W + h * HDIM;
    const float* Kbase = qkv + DMODEL     + h * HDIM;
    const float* Vbase = qkv + 2 * DMODEL + h * HDIM;

    float2 q2 = *(const float2*)(qrow + 2 * l);
    q_sh[w][2 * l]     = q2.x;
    q_sh[w][2 * l + 1] = q2.y;
    __syncwarp();

    float sloc[3];
    float m = -CUDART_INF_F;
#pragma unroll
    for (int j = 0; j < 3; j++) {
        const int o = l + 32 * j;
        float s = -CUDART_INF_F;
        if (o < NO) {
            const int idx = n - offs_sh[o];
            if (idx >= 0) {
                const float* krow = Kbase + (size_t)idx * QKV_W;
                float a = 0.0f;
#pragma unroll
                for (int d = 0; d < HDIM; d += 4) {
                    float4 kv = *(const float4*)(krow + d);
                    float4 qv = *(const float4*)(&q_sh[w][d]);
                    a += kv.x * qv.x + kv.y * qv.y + kv.z * qv.z + kv.w * qv.w;
                }
                s = a * 0.125f + pos_bias[o * NHEAD + h];
            }
        }
        sloc[j] = s;
        m = fmaxf(m, s);
    }
#pragma unroll
    for (int off = 16; off > 0; off >>= 1)
        m = fmaxf(m, __shfl_xor_sync(0xFFFFFFFFu, m, off));

    float ssum = 0.0f;
    float eloc[3];
#pragma unroll
    for (int j = 0; j < 3; j++) {
        float e = (sloc[j] == -CUDART_INF_F) ? 0.0f : __expf(sloc[j] - m);
        eloc[j] = e;
        ssum += e;
    }
#pragma unroll
    for (int off = 16; off > 0; off >>= 1)
        ssum += __shfl_xor_sync(0xFFFFFFFFu, ssum, off);

    const float inv = 1.0f / ssum;
#pragma unroll
    for (int j = 0; j < 3; j++) {
        const int o = l + 32 * j;
        if (o < NO) sc_sh[w][o] = eloc[j] * inv;
    }
    __syncwarp();

    float ax = 0.0f, ay = 0.0f;
    for (int o = 0; o < NO; o++) {
        const float a = sc_sh[w][o];
        int idx = n - offs_sh[o];
        if (idx < 0) idx = 0;
        const float2 v2 = *(const float2*)(Vbase + (size_t)idx * QKV_W + 2 * l);
        ax += a * v2.x;
        ay += a * v2.y;
    }

    const int col = h * HDIM + 2 * l;
    const float2 g = *(const float2*)(gate + (size_t)n * DMODEL + col);
    float2 r;
    r.x = rna_tf32(ax * g.x);   // pre-round: out-proj reads this as tf32 A
    r.y = rna_tf32(ay * g.y);
    *(float2*)(attn_out + (size_t)n * DMODEL + col) = r;
}

// ---------------------------------------------------------------------------
// Launch
// ---------------------------------------------------------------------------
extern "C" void kernel_launch(void* const* d_in, const int* in_sizes, int n_in,
                              void* d_out, int out_size)
{
    const float* x        = (const float*)d_in[0];
    const float* Wqkv     = (const float*)d_in[1];
    const float* bqkv     = (const float*)d_in[2];
    const float* Wgate    = (const float*)d_in[3];
    const float* bgate    = (const float*)d_in[4];
    const float* Wout     = (const float*)d_in[5];
    const float* bout     = (const float*)d_in[6];
    const float* pos_bias = (const float*)d_in[7];
    const int*   offsets  = (const int*)d_in[8];
    const int NO = in_sizes[8];

    float *qkv_p, *gate_p, *attn_p, *xr_p, *wqkvr_p, *wgatr_p, *woutr_p;
    cudaGetSymbolAddress((void**)&qkv_p,   g_qkv);
    cudaGetSymbolAddress((void**)&gate_p,  g_gate);
    cudaGetSymbolAddress((void**)&attn_p,  g_attn);
    cudaGetSymbolAddress((void**)&xr_p,    g_xr);
    cudaGetSymbolAddress((void**)&wqkvr_p, g_wqkvr);
    cudaGetSymbolAddress((void**)&wgatr_p, g_wgatr);
    cudaGetSymbolAddress((void**)&woutr_p, g_woutr);

    // 0) tf32-round GEMM operands
    round_kernel<<<1024, 256>>>((const float4*)x,     (float4*)xr_p,    NSEQ  * DMODEL / 4);
    round_kernel<<<1024, 256>>>((const float4*)Wqkv,  (float4*)wqkvr_p, QKV_W * DMODEL / 4);
    round_kernel<<<512,  256>>>((const float4*)Wgate, (float4*)wgatr_p, DMODEL * DMODEL / 4);
    round_kernel<<<512,  256>>>((const float4*)Wout,  (float4*)woutr_p, DMODEL * DMODEL / 4);

    // 1) qkv = x @ Wqkv^T + bqkv
    mma_gemm<<<dim3(QKV_W / BN, NSEQ / BM), 256>>>(
        xr_p, wqkvr_p, bqkv, qkv_p, NSEQ, QKV_W, DMODEL, 0);

    // 2) gate = sigmoid(x @ Wgate^T + bgate)
    mma_gemm<<<dim3(DMODEL / BN, NSEQ / BM), 256>>>(
        xr_p, wgatr_p, bgate, gate_p, NSEQ, DMODEL, DMODEL, 1);

    // 3) attention + gate multiply (tf32-rounded output)
    attn_kernel<<<(NSEQ * NHEAD) / WPB, WPB * 32>>>(
        qkv_p, gate_p, pos_bias, offsets, attn_p, NO);

    // 4) out = (attn*gate) @ Wout^T + bout
    mma_gemm<<<dim3(DMODEL / BN, NSEQ / BM), 256>>>(
        attn_p, woutr_p, bout, (float*)d_out, NSEQ, DMODEL, DMODEL, 0);
}